// round 2
// baseline (speedup 1.0000x reference)
#include <cuda_runtime.h>
#include <math.h>

#define NR 12288
#define KD 512
#define FD 128
#define NB 8192
#define BLO (-6.0f)
#define BHI (6.0f)
#define NCH 192
#define CH 64

// packed fp32x2 FMA (sm_100+)
#define FMA_F32X2(d, a, b, c) \
    asm("fma.rn.f32x2 %0, %1, %2, %3;" : "=l"(d) : "l"(a), "l"(b), "l"(c))
#define PACK_DUP_F32X2(d, a) \
    asm("mov.b64 %0, {%1, %1};" : "=l"(d) : "f"(a))

// ---------------- device scratch ----------------
__device__ float g_w[FD * KD];
__device__ float g_z[NR * FD];
__device__ float g_zp[NR * FD];     // permuted z rows
__device__ float g_s[NR];
__device__ float g_t[NR];
__device__ int   g_cnt[NB];
__device__ int   g_bstart[NB + 1];
__device__ int   g_cursor[NB];
__device__ int   g_perm[NR];
__device__ float g_tp[NR];
__device__ float g_etp[NR];         // exp(t) permuted
__device__ float g_chZ[NCH * FD];
__device__ float g_chEZ[NCH * FD];
__device__ float g_chE[NCH];
__device__ float g_ofZ[NCH * FD];
__device__ float g_ofEZ[NCH * FD];
__device__ float g_ofE[NCH];
__device__ float g_PZ[(NR + 1) * FD];
__device__ float g_SEZ[(NR + 1) * FD];
__device__ float g_SE[NR + 1];

__device__ __forceinline__ int bucket_of(float t) {
    float u = (t - BLO) * ((float)NB / (BHI - BLO));
    int b = (int)floorf(u);
    b = b < 0 ? 0 : b;
    b = b > NB - 1 ? NB - 1 : b;
    return b;
}

// ---------------- 1. weight-norm + zero histogram ----------------
__global__ void k_w(const float* __restrict__ v, const float* __restrict__ g) {
    int r = blockIdx.x, t = threadIdx.x;
    int gi = r * 128 + t;
    if (gi < NB) g_cnt[gi] = 0;
    float ss = 0.f;
    for (int c = t; c < KD; c += 128) { float a = v[r * KD + c]; ss += a * a; }
    __shared__ float red[4];
    #pragma unroll
    for (int o = 16; o; o >>= 1) ss += __shfl_xor_sync(0xffffffffu, ss, o);
    if ((t & 31) == 0) red[t >> 5] = ss;
    __syncthreads();
    float tot = red[0] + red[1] + red[2] + red[3];
    float sc = g[r] / sqrtf(tot);
    for (int c = t; c < KD; c += 128) g_w[r * KD + c] = v[r * KD + c] * sc;
}

// ---------------- 2. GEMM z = x@w^T + b  (FFMA2, fused s/t epilogue) --------
// tile 64(M) x 128(N) x 16(K), 256 threads, 4x8 microtile (4x4 f32x2)
__global__ void __launch_bounds__(256, 2)
k_gemm(const float* __restrict__ x, const float* __restrict__ b,
       const float* __restrict__ att) {
    __shared__ float As[16][64];
    __shared__ float Bs[16][128];
    int tid = threadIdx.x;
    int m0 = blockIdx.x * 64;
    int ty = tid >> 4, tx = tid & 15;
    int arow = tid >> 2, aseg = tid & 3;

    unsigned long long acc[4][4];
    #pragma unroll
    for (int i = 0; i < 4; i++)
        #pragma unroll
        for (int j = 0; j < 4; j++) acc[i][j] = 0ull;

    for (int k0 = 0; k0 < KD; k0 += 16) {
        float4 av = *(const float4*)(x + (size_t)(m0 + arow) * KD + k0 + aseg * 4);
        As[aseg * 4 + 0][arow] = av.x;
        As[aseg * 4 + 1][arow] = av.y;
        As[aseg * 4 + 2][arow] = av.z;
        As[aseg * 4 + 3][arow] = av.w;
        #pragma unroll
        for (int l = 0; l < 2; l++) {
            int e = tid + l * 256;
            int brow = e >> 2, bseg = e & 3;
            float4 bv = *(const float4*)(g_w + (size_t)brow * KD + k0 + bseg * 4);
            Bs[bseg * 4 + 0][brow] = bv.x;
            Bs[bseg * 4 + 1][brow] = bv.y;
            Bs[bseg * 4 + 2][brow] = bv.z;
            Bs[bseg * 4 + 3][brow] = bv.w;
        }
        __syncthreads();
        #pragma unroll
        for (int kk = 0; kk < 16; kk++) {
            float4 a4 = *(float4*)(&As[kk][ty * 4]);
            ulonglong2 b0 = *(ulonglong2*)(&Bs[kk][tx * 4]);
            ulonglong2 b1 = *(ulonglong2*)(&Bs[kk][64 + tx * 4]);
            float ar[4] = {a4.x, a4.y, a4.z, a4.w};
            #pragma unroll
            for (int im = 0; im < 4; im++) {
                unsigned long long ap;
                PACK_DUP_F32X2(ap, ar[im]);
                FMA_F32X2(acc[im][0], ap, b0.x, acc[im][0]);
                FMA_F32X2(acc[im][1], ap, b0.y, acc[im][1]);
                FMA_F32X2(acc[im][2], ap, b1.x, acc[im][2]);
                FMA_F32X2(acc[im][3], ap, b1.y, acc[im][3]);
            }
        }
        __syncthreads();
    }

    // bias + store z + fused s,t partials
    float4 bb0 = *(const float4*)(b + tx * 4);
    float4 bb1 = *(const float4*)(b + 64 + tx * 4);
    float4 as0 = *(const float4*)(att + tx * 4);
    float4 as1 = *(const float4*)(att + 64 + tx * 4);
    float4 ad0 = *(const float4*)(att + FD + tx * 4);
    float4 ad1 = *(const float4*)(att + FD + 64 + tx * 4);

    #pragma unroll
    for (int im = 0; im < 4; im++) {
        int row = m0 + ty * 4 + im;
        float2 p0 = *(float2*)&acc[im][0];
        float2 p1 = *(float2*)&acc[im][1];
        float2 p2 = *(float2*)&acc[im][2];
        float2 p3 = *(float2*)&acc[im][3];
        float z0 = p0.x + bb0.x, z1 = p0.y + bb0.y;
        float z2 = p1.x + bb0.z, z3 = p1.y + bb0.w;
        float z4 = p2.x + bb1.x, z5 = p2.y + bb1.y;
        float z6 = p3.x + bb1.z, z7 = p3.y + bb1.w;
        *(float4*)(g_z + (size_t)row * FD + tx * 4)      = make_float4(z0, z1, z2, z3);
        *(float4*)(g_z + (size_t)row * FD + 64 + tx * 4) = make_float4(z4, z5, z6, z7);
        float sp = z0 * as0.x + z1 * as0.y + z2 * as0.z + z3 * as0.w
                 + z4 * as1.x + z5 * as1.y + z6 * as1.z + z7 * as1.w;
        float tp = z0 * ad0.x + z1 * ad0.y + z2 * ad0.z + z3 * ad0.w
                 + z4 * ad1.x + z5 * ad1.y + z6 * ad1.z + z7 * ad1.w;
        #pragma unroll
        for (int o = 8; o; o >>= 1) {
            sp += __shfl_xor_sync(0xffffffffu, sp, o);
            tp += __shfl_xor_sync(0xffffffffu, tp, o);
        }
        if (tx == 0) { g_s[row] = sp; g_t[row] = tp; }
    }
}

// ---------------- 3. bucket counting sort of t ----------------
__global__ void k_hist() {
    int j = blockIdx.x * 256 + threadIdx.x;
    if (j < NR) atomicAdd(&g_cnt[bucket_of(g_t[j])], 1);
}

__global__ void k_prefix() {
    __shared__ int part[256];
    int t = threadIdx.x;
    int base = t * 32;
    int s = 0;
    for (int i = 0; i < 32; i++) s += g_cnt[base + i];
    part[t] = s;
    __syncthreads();
    if (t == 0) {
        int run = 0;
        for (int i = 0; i < 256; i++) { int c = part[i]; part[i] = run; run += c; }
    }
    __syncthreads();
    int run = part[t];
    for (int i = 0; i < 32; i++) {
        g_bstart[base + i] = run;
        g_cursor[base + i] = run;
        run += g_cnt[base + i];
    }
    if (t == 255) g_bstart[NB] = NR;
}

__global__ void k_scatter() {
    int j = blockIdx.x * 256 + threadIdx.x;
    if (j >= NR) return;
    float tv = g_t[j];
    int b = bucket_of(tv);
    int slot = atomicAdd(&g_cursor[b], 1);
    g_perm[slot] = j;
    g_tp[slot] = tv;
}

// materialize permuted z rows (coalesced reads downstream) + exp(t)
__global__ void k_permz() {
    int gid = blockIdx.x * 256 + threadIdx.x;
    int slot = gid >> 5, lane = gid & 31;
    if (slot >= NR) return;
    int src = g_perm[slot];
    float4 v = *(const float4*)(g_z + (size_t)src * FD + lane * 4);
    *(float4*)(g_zp + (size_t)slot * FD + lane * 4) = v;
    if (lane == 0) g_etp[slot] = expf(g_tp[slot]);
}

// ---------------- 4. chunked scans over bucket-ordered z rows ----------------
__global__ void k_s1() {
    int c = blockIdx.x, f = threadIdx.x;
    int base = c * CH;
    float aZ = 0.f, aEZ = 0.f, aE = 0.f;
    #pragma unroll 8
    for (int r = 0; r < CH; r++) {
        int m = base + r;
        float et = g_etp[m];
        float zv = g_zp[(size_t)m * FD + f];
        aZ += zv;
        aEZ = fmaf(et, zv, aEZ);
        aE += et;
    }
    g_chZ[c * FD + f] = aZ;
    g_chEZ[c * FD + f] = aEZ;
    if (f == 0) g_chE[c] = aE;
}

__global__ void k_s2() {
    int f = threadIdx.x;
    float run = 0.f;
    for (int c = 0; c < NCH; c++) { g_ofZ[c * FD + f] = run; run += g_chZ[c * FD + f]; }
    g_PZ[(size_t)NR * FD + f] = run;
    float re = 0.f;
    for (int c = NCH - 1; c >= 0; c--) { g_ofEZ[c * FD + f] = re; re += g_chEZ[c * FD + f]; }
    g_SEZ[(size_t)NR * FD + f] = 0.f;
    if (f == 0) {
        float rE = 0.f;
        for (int c = NCH - 1; c >= 0; c--) { g_ofE[c] = rE; rE += g_chE[c]; }
        g_SE[NR] = 0.f;
    }
}

__global__ void k_s3() {
    int c = blockIdx.x, f = threadIdx.x, base = c * CH;
    float aZ = g_ofZ[c * FD + f];
    #pragma unroll 8
    for (int r = 0; r < CH; r++) {
        int m = base + r;
        g_PZ[(size_t)m * FD + f] = aZ;
        aZ += g_zp[(size_t)m * FD + f];
    }
    float aEZ = g_ofEZ[c * FD + f];
    float aE = g_ofE[c];
    #pragma unroll 8
    for (int r = CH - 1; r >= 0; r--) {
        int m = base + r;
        float et = g_etp[m];
        aEZ = fmaf(et, g_zp[(size_t)m * FD + f], aEZ);
        g_SEZ[(size_t)m * FD + f] = aEZ;
        if (f == 0) { aE += et; g_SE[m] = aE; }
    }
}

// ---------------- 5. per-row combine + boundary bucket + row softmax --------
__global__ void k_final(float* __restrict__ out) {
    __shared__ float rmax[4], rsum[4];
    int f = threadIdx.x, lane = f & 31, wid = f >> 5;
    #pragma unroll 1
    for (int rr = 0; rr < 4; rr++) {
        int i = blockIdx.x * 4 + rr;
        float si = g_s[i];
        float th = -si;
        float es = expf(si);
        int b = bucket_of(th);
        int klo = g_bstart[b], khi = g_bstart[b + 1];
        float D = (float)klo + es * g_SE[khi];
        float num = g_PZ[(size_t)klo * FD + f] + es * g_SEZ[(size_t)khi * FD + f];
        for (int m = klo; m < khi; m++) {
            float tj = g_tp[m];
            float zv = g_zp[(size_t)m * FD + f];
            if (tj <= th) { num += zv; D += 1.f; }
            else { float w = es * g_etp[m]; num = fmaf(w, zv, num); D += w; }
        }
        float z2 = num / D + g_z[(size_t)i * FD + f];
        float mx = z2;
        #pragma unroll
        for (int o = 16; o; o >>= 1) mx = fmaxf(mx, __shfl_xor_sync(0xffffffffu, mx, o));
        if (lane == 0) rmax[wid] = mx;
        __syncthreads();
        mx = fmaxf(fmaxf(rmax[0], rmax[1]), fmaxf(rmax[2], rmax[3]));
        float ex = expf(z2 - mx);
        float sm = ex;
        #pragma unroll
        for (int o = 16; o; o >>= 1) sm += __shfl_xor_sync(0xffffffffu, sm, o);
        if (lane == 0) rsum[wid] = sm;
        __syncthreads();
        sm = rsum[0] + rsum[1] + rsum[2] + rsum[3];
        out[(size_t)i * FD + f] = ex / sm;
        __syncthreads();
    }
}

// ---------------- launch ----------------
extern "C" void kernel_launch(void* const* d_in, const int* in_sizes, int n_in,
                              void* d_out, int out_size) {
    const float* x   = (const float*)d_in[0];
    const float* v   = (const float*)d_in[1];
    const float* g   = (const float*)d_in[2];
    const float* b   = (const float*)d_in[3];
    const float* att = (const float*)d_in[4];
    float* out = (float*)d_out;

    k_w<<<FD, 128>>>(v, g);
    k_gemm<<<NR / 64, 256>>>(x, b, att);
    k_hist<<<NR / 256, 256>>>();
    k_prefix<<<1, 256>>>();
    k_scatter<<<NR / 256, 256>>>();
    k_permz<<<NR * 32 / 256, 256>>>();
    k_s1<<<NCH, FD>>>();
    k_s2<<<1, FD>>>();
    k_s3<<<NCH, FD>>>();
    k_final<<<NR / 4, FD>>>(out);
}

// round 4
// speedup vs baseline: 1.1928x; 1.1928x over previous
#include <cuda_runtime.h>
#include <cuda_bf16.h>
#include <math.h>
#include <stdint.h>

#define NR 12288
#define KD 512
#define FD 128
#define NB 8192
#define BLO (-6.0f)
#define BHI (6.0f)
#define NCH 192
#define CH 64

// ---------------- device scratch ----------------
__device__ __nv_bfloat16 g_wh[FD * KD];
__device__ __nv_bfloat16 g_wl[FD * KD];
__device__ float g_z[NR * FD];
__device__ float g_zp[NR * FD];
__device__ float g_s[NR];
__device__ float g_t[NR];
__device__ int   g_cnt[NB];
__device__ int   g_bstart[NB + 1];
__device__ int   g_cursor[NB];
__device__ int   g_perm[NR];
__device__ float g_tp[NR];
__device__ float g_etp[NR];
__device__ float g_chZ[NCH * FD];
__device__ float g_chEZ[NCH * FD];
__device__ float g_chE[NCH];
__device__ float g_ofZ[NCH * FD];
__device__ float g_ofEZ[NCH * FD];
__device__ float g_ofE[NCH];
__device__ float g_PZ[(NR + 1) * FD];
__device__ float g_SEZ[(NR + 1) * FD];
__device__ float g_SE[NR + 1];

__device__ __forceinline__ int bucket_of(float t) {
    float u = (t - BLO) * ((float)NB / (BHI - BLO));
    int b = (int)floorf(u);
    b = b < 0 ? 0 : b;
    b = b > NB - 1 ? NB - 1 : b;
    return b;
}

__device__ __forceinline__ uint32_t smem_u32(const void* p) {
    uint32_t a;
    asm("{ .reg .u64 t; cvta.to.shared.u64 t, %1; cvt.u32.u64 %0, t; }" : "=r"(a) : "l"(p));
    return a;
}

#define LDSM4(r, a) \
    asm volatile("ldmatrix.sync.aligned.m8n8.x4.shared.b16 {%0,%1,%2,%3}, [%4];" \
        : "=r"((r)[0]), "=r"((r)[1]), "=r"((r)[2]), "=r"((r)[3]) : "r"(a))

#define MMA16816(d, a, b0, b1) \
    asm volatile("mma.sync.aligned.m16n8k16.row.col.f32.bf16.bf16.f32 " \
        "{%0,%1,%2,%3},{%4,%5,%6,%7},{%8,%9},{%0,%1,%2,%3};" \
        : "+f"((d)[0]), "+f"((d)[1]), "+f"((d)[2]), "+f"((d)[3]) \
        : "r"((a)[0]), "r"((a)[1]), "r"((a)[2]), "r"((a)[3]), "r"(b0), "r"(b1))

__device__ __forceinline__ uint32_t packbf(__nv_bfloat16 a, __nv_bfloat16 b) {
    return (uint32_t)__bfloat16_as_ushort(a) | ((uint32_t)__bfloat16_as_ushort(b) << 16);
}

// ---------------- 1. weight-norm -> bf16 split, zero histogram -------------
__global__ void k_w(const float* __restrict__ v, const float* __restrict__ g) {
    int r = blockIdx.x, t = threadIdx.x;
    int gi = r * 64 + t;
    if (gi < NB) g_cnt[gi] = 0;
    float ss = 0.f;
    for (int c = t; c < KD; c += 128) { float a = v[r * KD + c]; ss += a * a; }
    __shared__ float red[4];
    #pragma unroll
    for (int o = 16; o; o >>= 1) ss += __shfl_xor_sync(0xffffffffu, ss, o);
    if ((t & 31) == 0) red[t >> 5] = ss;
    __syncthreads();
    float tot = red[0] + red[1] + red[2] + red[3];
    float sc = g[r] / sqrtf(tot);
    for (int c = t; c < KD; c += 128) {
        float wv = v[r * KD + c] * sc;
        __nv_bfloat16 hi = __float2bfloat16(wv);
        g_wh[r * KD + c] = hi;
        g_wl[r * KD + c] = __float2bfloat16(wv - __bfloat162float(hi));
    }
}

// ---------------- 2. mma.sync bf16-split GEMM + fused epilogue -------------
// CTA: 128(M) x 128(N), K chunks of 64. 8 warps = 4(M) x 2(N), warp 32x64.
#define RSTR 144                       // padded smem row stride bytes (72 bf16)
#define SA_H 0
#define SA_L (128 * RSTR)
#define SB_H (2 * 128 * RSTR)
#define SB_L (3 * 128 * RSTR)
#define SP_S (4 * 128 * RSTR)          // 73728
#define SP_T (SP_S + 1024)
#define SM_TOT (SP_T + 1024)           // 75776

__global__ void __launch_bounds__(256, 1)
k_gemm(const float* __restrict__ x, const float* __restrict__ bias,
       const float* __restrict__ att) {
    extern __shared__ char smem[];
    uint32_t sb = smem_u32(smem);
    int tid = threadIdx.x, lane = tid & 31, wid = tid >> 5;
    int m0 = blockIdx.x * 128;
    int warp_m = wid & 3, warp_n = wid >> 2;

    float acc[2][8][4];
    #pragma unroll
    for (int i = 0; i < 2; i++)
        #pragma unroll
        for (int j = 0; j < 8; j++)
            #pragma unroll
            for (int q = 0; q < 4; q++) acc[i][j][q] = 0.f;

    int lrow = tid >> 1, lcol0 = (tid & 1) * 32;
    const float* xrow = x + (size_t)(m0 + lrow) * KD + lcol0;
    const __nv_bfloat16* whr = g_wh + (size_t)lrow * KD + lcol0;
    const __nv_bfloat16* wlr = g_wl + (size_t)lrow * KD + lcol0;
    char* arow_h = smem + SA_H + lrow * RSTR + lcol0 * 2;
    char* arow_l = smem + SA_L + lrow * RSTR + lcol0 * 2;
    char* brow_h = smem + SB_H + lrow * RSTR + lcol0 * 2;
    char* brow_l = smem + SB_L + lrow * RSTR + lcol0 * 2;

    // ldmatrix lane addressing
    int a_r = warp_m * 32 + (lane & 7) + ((lane & 8) ? 8 : 0);
    int a_c = (lane & 16) ? 8 : 0;
    int b_r = warp_n * 64 + (lane & 7) + ((lane & 16) ? 8 : 0);
    int b_c = (lane & 8) ? 8 : 0;

    for (int c = 0; c < 8; c++) {
        int k0 = c * 64;
        #pragma unroll
        for (int j = 0; j < 8; j++) {
            float4 f = *(const float4*)(xrow + k0 + j * 4);
            __nv_bfloat16 h0 = __float2bfloat16(f.x), h1 = __float2bfloat16(f.y);
            __nv_bfloat16 h2 = __float2bfloat16(f.z), h3 = __float2bfloat16(f.w);
            __nv_bfloat16 l0 = __float2bfloat16(f.x - __bfloat162float(h0));
            __nv_bfloat16 l1 = __float2bfloat16(f.y - __bfloat162float(h1));
            __nv_bfloat16 l2 = __float2bfloat16(f.z - __bfloat162float(h2));
            __nv_bfloat16 l3 = __float2bfloat16(f.w - __bfloat162float(h3));
            *(uint2*)(arow_h + j * 8) = make_uint2(packbf(h0, h1), packbf(h2, h3));
            *(uint2*)(arow_l + j * 8) = make_uint2(packbf(l0, l1), packbf(l2, l3));
        }
        #pragma unroll
        for (int j = 0; j < 4; j++) {
            *(uint4*)(brow_h + j * 16) = *(const uint4*)(whr + k0 + j * 8);
            *(uint4*)(brow_l + j * 16) = *(const uint4*)(wlr + k0 + j * 8);
        }
        __syncthreads();

        #pragma unroll
        for (int ks = 0; ks < 4; ks++) {
            int ko = ks * 16;
            uint32_t ah[2][4], al[2][4];
            #pragma unroll
            for (int mf = 0; mf < 2; mf++) {
                uint32_t aa = sb + (a_r + mf * 16) * RSTR + (ko + a_c) * 2;
                LDSM4(ah[mf], aa + SA_H);
                LDSM4(al[mf], aa + SA_L);
            }
            #pragma unroll
            for (int nf2 = 0; nf2 < 4; nf2++) {
                uint32_t bh[4], bl[4];
                uint32_t ba = sb + (b_r + nf2 * 16) * RSTR + (ko + b_c) * 2;
                LDSM4(bh, ba + SB_H);
                LDSM4(bl, ba + SB_L);
                #pragma unroll
                for (int mf = 0; mf < 2; mf++) {
                    MMA16816(acc[mf][2 * nf2],     ah[mf], bh[0], bh[1]);
                    MMA16816(acc[mf][2 * nf2],     ah[mf], bl[0], bl[1]);
                    MMA16816(acc[mf][2 * nf2],     al[mf], bh[0], bh[1]);
                    MMA16816(acc[mf][2 * nf2 + 1], ah[mf], bh[2], bh[3]);
                    MMA16816(acc[mf][2 * nf2 + 1], ah[mf], bl[2], bl[3]);
                    MMA16816(acc[mf][2 * nf2 + 1], al[mf], bh[2], bh[3]);
                }
            }
        }
        __syncthreads();
    }

    // epilogue: bias, z store, s/t partials
    #pragma unroll
    for (int r4 = 0; r4 < 4; r4++) {
        int mf = r4 >> 1, half = r4 & 1;
        int rloc = warp_m * 32 + mf * 16 + half * 8 + (lane >> 2);
        int row_g = m0 + rloc;
        float sp = 0.f, tp = 0.f;
        #pragma unroll
        for (int nf = 0; nf < 8; nf++) {
            int col = warp_n * 64 + nf * 8 + (lane & 3) * 2;
            float z0 = acc[mf][nf][half * 2]     + bias[col];
            float z1 = acc[mf][nf][half * 2 + 1] + bias[col + 1];
            *(float2*)(g_z + (size_t)row_g * FD + col) = make_float2(z0, z1);
            sp = fmaf(z0, att[col], fmaf(z1, att[col + 1], sp));
            tp = fmaf(z0, att[FD + col], fmaf(z1, att[FD + col + 1], tp));
        }
        sp += __shfl_xor_sync(0xffffffffu, sp, 1);
        sp += __shfl_xor_sync(0xffffffffu, sp, 2);
        tp += __shfl_xor_sync(0xffffffffu, tp, 1);
        tp += __shfl_xor_sync(0xffffffffu, tp, 2);
        if ((lane & 3) == 0) {
            *(float*)(smem + SP_S + (warp_n * 128 + rloc) * 4) = sp;
            *(float*)(smem + SP_T + (warp_n * 128 + rloc) * 4) = tp;
        }
    }
    __syncthreads();
    if (tid < 128) {
        float s = *(float*)(smem + SP_S + tid * 4) + *(float*)(smem + SP_S + (128 + tid) * 4);
        float t = *(float*)(smem + SP_T + tid * 4) + *(float*)(smem + SP_T + (128 + tid) * 4);
        g_s[m0 + tid] = s;
        g_t[m0 + tid] = t;
        atomicAdd(&g_cnt[bucket_of(t)], 1);
    }
}

// ---------------- 3. parallel bucket prefix ----------------
__global__ void k_prefix() {
    __shared__ int wsum[8];
    int t = threadIdx.x, lane = t & 31, wid = t >> 5;
    int c[32];
    const int4* c4 = (const int4*)g_cnt;
    int s = 0;
    #pragma unroll
    for (int i = 0; i < 8; i++) {
        int4 v = c4[t * 8 + i];
        c[4 * i] = v.x; c[4 * i + 1] = v.y; c[4 * i + 2] = v.z; c[4 * i + 3] = v.w;
        s += v.x + v.y + v.z + v.w;
    }
    int sc = s;
    #pragma unroll
    for (int o = 1; o < 32; o <<= 1) {
        int n = __shfl_up_sync(0xffffffffu, sc, o);
        if (lane >= o) sc += n;
    }
    if (lane == 31) wsum[wid] = sc;
    __syncthreads();
    int woff = 0;
    #pragma unroll
    for (int i = 0; i < 8; i++) if (i < wid) woff += wsum[i];
    int run = woff + sc - s;
    #pragma unroll
    for (int i = 0; i < 32; i++) {
        g_bstart[t * 32 + i] = run;
        g_cursor[t * 32 + i] = run;
        run += c[i];
    }
    if (t == 255) g_bstart[NB] = NR;
}

__global__ void k_scatter() {
    int j = blockIdx.x * 256 + threadIdx.x;
    if (j >= NR) return;
    float tv = g_t[j];
    int b = bucket_of(tv);
    int slot = atomicAdd(&g_cursor[b], 1);
    g_perm[slot] = j;
    g_tp[slot] = tv;
}

__global__ void k_permz() {
    int gid = blockIdx.x * 256 + threadIdx.x;
    int slot = gid >> 5, lane = gid & 31;
    if (slot >= NR) return;
    int src = g_perm[slot];
    float4 v = *(const float4*)(g_z + (size_t)src * FD + lane * 4);
    *(float4*)(g_zp + (size_t)slot * FD + lane * 4) = v;
    if (lane == 0) g_etp[slot] = expf(g_tp[slot]);
}

// ---------------- 4. chunked scans ----------------
__global__ void k_s1() {
    int c = blockIdx.x, f = threadIdx.x;
    int base = c * CH;
    float aZ = 0.f, aEZ = 0.f, aE = 0.f;
    #pragma unroll 8
    for (int r = 0; r < CH; r++) {
        int m = base + r;
        float et = g_etp[m];
        float zv = g_zp[(size_t)m * FD + f];
        aZ += zv;
        aEZ = fmaf(et, zv, aEZ);
        aE += et;
    }
    g_chZ[c * FD + f] = aZ;
    g_chEZ[c * FD + f] = aEZ;
    if (f == 0) g_chE[c] = aE;
}

__global__ void k_s2() {
    int f = threadIdx.x;
    float run = 0.f;
    #pragma unroll 8
    for (int c = 0; c < NCH; c++) { g_ofZ[c * FD + f] = run; run += g_chZ[c * FD + f]; }
    g_PZ[(size_t)NR * FD + f] = run;
    float re = 0.f;
    #pragma unroll 8
    for (int c = NCH - 1; c >= 0; c--) { g_ofEZ[c * FD + f] = re; re += g_chEZ[c * FD + f]; }
    g_SEZ[(size_t)NR * FD + f] = 0.f;
    if (f == 0) {
        float rE = 0.f;
        for (int c = NCH - 1; c >= 0; c--) { g_ofE[c] = rE; rE += g_chE[c]; }
        g_SE[NR] = 0.f;
    }
}

__global__ void k_s3() {
    int c = blockIdx.x, f = threadIdx.x, base = c * CH;
    float aZ = g_ofZ[c * FD + f];
    #pragma unroll 8
    for (int r = 0; r < CH; r++) {
        int m = base + r;
        g_PZ[(size_t)m * FD + f] = aZ;
        aZ += g_zp[(size_t)m * FD + f];
    }
    float aEZ = g_ofEZ[c * FD + f];
    float aE = g_ofE[c];
    #pragma unroll 8
    for (int r = CH - 1; r >= 0; r--) {
        int m = base + r;
        float et = g_etp[m];
        aEZ = fmaf(et, g_zp[(size_t)m * FD + f], aEZ);
        g_SEZ[(size_t)m * FD + f] = aEZ;
        if (f == 0) { aE += et; g_SE[m] = aE; }
    }
}

// ---------------- 5. per-row combine + row softmax ----------------
__global__ void k_final(float* __restrict__ out) {
    __shared__ float rmax[4], rsum[4];
    int f = threadIdx.x, lane = f & 31, wid = f >> 5;
    #pragma unroll 1
    for (int rr = 0; rr < 4; rr++) {
        int i = blockIdx.x * 4 + rr;
        float si = g_s[i];
        float th = -si;
        float es = expf(si);
        int b = bucket_of(th);
        int klo = g_bstart[b], khi = g_bstart[b + 1];
        float D = (float)klo + es * g_SE[khi];
        float num = g_PZ[(size_t)klo * FD + f] + es * g_SEZ[(size_t)khi * FD + f];
        for (int m = klo; m < khi; m++) {
            float tj = g_tp[m];
            float zv = g_zp[(size_t)m * FD + f];
            if (tj <= th) { num += zv; D += 1.f; }
            else { float w = es * g_etp[m]; num = fmaf(w, zv, num); D += w; }
        }
        float z2 = num / D + g_z[(size_t)i * FD + f];
        float mx = z2;
        #pragma unroll
        for (int o = 16; o; o >>= 1) mx = fmaxf(mx, __shfl_xor_sync(0xffffffffu, mx, o));
        if (lane == 0) rmax[wid] = mx;
        __syncthreads();
        mx = fmaxf(fmaxf(rmax[0], rmax[1]), fmaxf(rmax[2], rmax[3]));
        float ex = expf(z2 - mx);
        float sm = ex;
        #pragma unroll
        for (int o = 16; o; o >>= 1) sm += __shfl_xor_sync(0xffffffffu, sm, o);
        if (lane == 0) rsum[wid] = sm;
        __syncthreads();
        sm = rsum[0] + rsum[1] + rsum[2] + rsum[3];
        out[(size_t)i * FD + f] = ex / sm;
        __syncthreads();
    }
}

// ---------------- launch ----------------
extern "C" void kernel_launch(void* const* d_in, const int* in_sizes, int n_in,
                              void* d_out, int out_size) {
    const float* x   = (const float*)d_in[0];
    const float* v   = (const float*)d_in[1];
    const float* g   = (const float*)d_in[2];
    const float* b   = (const float*)d_in[3];
    const float* att = (const float*)d_in[4];
    float* out = (float*)d_out;

    static int smem_set = 0;
    if (!smem_set) {
        cudaFuncSetAttribute(k_gemm, cudaFuncAttributeMaxDynamicSharedMemorySize, SM_TOT);
        smem_set = 1;
    }

    k_w<<<FD, 128>>>(v, g);
    k_gemm<<<NR / 128, 256, SM_TOT>>>(x, b, att);
    k_prefix<<<1, 256>>>();
    k_scatter<<<NR / 256, 256>>>();
    k_permz<<<NR * 32 / 256, 256>>>();
    k_s1<<<NCH, FD>>>();
    k_s2<<<1, FD>>>();
    k_s3<<<NCH, FD>>>();
    k_final<<<NR / 4, FD>>>(out);
}

// round 7
// speedup vs baseline: 1.6274x; 1.3643x over previous
#include <cuda_runtime.h>
#include <cuda_bf16.h>
#include <math.h>
#include <stdint.h>

#define NR 12288
#define KD 512
#define FD 128
#define NB 8192
#define BLO (-6.0f)
#define BHI (6.0f)
#define NCH 96
#define CH 128

// ---------------- device scratch ----------------
__device__ __nv_bfloat16 g_wh[FD * KD];
__device__ __nv_bfloat16 g_wl[FD * KD];
__device__ float g_z[NR * FD];
__device__ float g_zp[NR * FD];
__device__ float g_s[NR];
__device__ float g_t[NR];
__device__ int   g_cnt[NB];
__device__ int   g_bstart[NB + 1];
__device__ int   g_cursor[NB];
__device__ float g_tp[NR];
__device__ float g_etp[NR];
__device__ float g_chZ[NCH * FD];
__device__ float g_chEZ[NCH * FD];
__device__ float g_chE[NCH];
__device__ float g_ofZ[NCH * FD];
__device__ float g_ofEZ[NCH * FD];
__device__ float g_ofE[NCH];
__device__ float g_PZ[(NR + 1) * FD];
__device__ float g_SEZ[(NR + 1) * FD];
__device__ float g_SE[NR + 1];

__device__ __forceinline__ int bucket_of(float t) {
    float u = (t - BLO) * ((float)NB / (BHI - BLO));
    int b = (int)floorf(u);
    b = b < 0 ? 0 : b;
    b = b > NB - 1 ? NB - 1 : b;
    return b;
}

__device__ __forceinline__ uint32_t smem_u32(const void* p) {
    uint32_t a;
    asm("{ .reg .u64 t; cvta.to.shared.u64 t, %1; cvt.u32.u64 %0, t; }" : "=r"(a) : "l"(p));
    return a;
}

#define LDSM4(r, a) \
    asm volatile("ldmatrix.sync.aligned.m8n8.x4.shared.b16 {%0,%1,%2,%3}, [%4];" \
        : "=r"((r)[0]), "=r"((r)[1]), "=r"((r)[2]), "=r"((r)[3]) : "r"(a))

#define MMA16816(d, a, b0, b1) \
    asm volatile("mma.sync.aligned.m16n8k16.row.col.f32.bf16.bf16.f32 " \
        "{%0,%1,%2,%3},{%4,%5,%6,%7},{%8,%9},{%0,%1,%2,%3};" \
        : "+f"((d)[0]), "+f"((d)[1]), "+f"((d)[2]), "+f"((d)[3]) \
        : "r"((a)[0]), "r"((a)[1]), "r"((a)[2]), "r"((a)[3]), "r"(b0), "r"(b1))

__device__ __forceinline__ uint32_t packbf(__nv_bfloat16 a, __nv_bfloat16 b) {
    return (uint32_t)__bfloat16_as_ushort(a) | ((uint32_t)__bfloat16_as_ushort(b) << 16);
}

// ---------------- 1. weight-norm -> bf16 split, zero histogram -------------
__global__ void k_w(const float* __restrict__ v, const float* __restrict__ g) {
    int r = blockIdx.x, t = threadIdx.x;
    int gi = r * 64 + t;
    if (gi < NB) g_cnt[gi] = 0;
    float ss = 0.f;
    for (int c = t; c < KD; c += 128) { float a = v[r * KD + c]; ss += a * a; }
    __shared__ float red[4];
    #pragma unroll
    for (int o = 16; o; o >>= 1) ss += __shfl_xor_sync(0xffffffffu, ss, o);
    if ((t & 31) == 0) red[t >> 5] = ss;
    __syncthreads();
    float tot = red[0] + red[1] + red[2] + red[3];
    float sc = g[r] / sqrtf(tot);
    for (int c = t; c < KD; c += 128) {
        float wv = v[r * KD + c] * sc;
        __nv_bfloat16 hi = __float2bfloat16(wv);
        g_wh[r * KD + c] = hi;
        g_wl[r * KD + c] = __float2bfloat16(wv - __bfloat162float(hi));
    }
}

// ---------------- 2. mma.sync bf16-split GEMM + fused epilogue -------------
// CTA: 128(M) x 128(N), K chunks of 64. 16 warps = 4(M) x 4(N), warp 32x32.
// Register-staged prefetch of next chunk overlaps global latency with MMAs.
#define RSTR 144
#define SA_H 0
#define SA_L (128 * RSTR)
#define SB_H (2 * 128 * RSTR)
#define SB_L (3 * 128 * RSTR)
#define SP_S (4 * 128 * RSTR)
#define SP_T (SP_S + 2048)
#define SM_TOT (SP_T + 2048)

__global__ void __launch_bounds__(512, 1)
k_gemm(const float* __restrict__ x, const float* __restrict__ bias,
       const float* __restrict__ att) {
    extern __shared__ char smem[];
    uint32_t sb = smem_u32(smem);
    int tid = threadIdx.x, lane = tid & 31, wid = tid >> 5;
    int m0 = blockIdx.x * 128;
    int warp_m = wid & 3, warp_n = wid >> 2;

    float acc[2][4][4];
    #pragma unroll
    for (int i = 0; i < 2; i++)
        #pragma unroll
        for (int j = 0; j < 4; j++)
            #pragma unroll
            for (int q = 0; q < 4; q++) acc[i][j][q] = 0.f;

    int lrow = tid >> 2, lcol0 = (tid & 3) * 16;
    const float* xrow = x + (size_t)(m0 + lrow) * KD + lcol0;
    const __nv_bfloat16* whp = g_wh + (size_t)lrow * KD + lcol0;
    const __nv_bfloat16* wlp = g_wl + (size_t)lrow * KD + lcol0;
    char* arow_h = smem + SA_H + lrow * RSTR + lcol0 * 2;
    char* arow_l = smem + SA_L + lrow * RSTR + lcol0 * 2;
    char* brow_h = smem + SB_H + lrow * RSTR + lcol0 * 2;
    char* brow_l = smem + SB_L + lrow * RSTR + lcol0 * 2;

    int a_rb = warp_m * 32 + (lane & 15);
    int a_c  = (lane & 16) ? 8 : 0;
    int b_rb = warp_n * 32 + (lane & 7) + ((lane & 16) ? 8 : 0);
    int b_c  = (lane & 8) ? 8 : 0;

    float4 xr[4];
    uint4 wh2[2], wl2[2];
    // prefetch chunk 0
    #pragma unroll
    for (int j = 0; j < 4; j++) xr[j] = *(const float4*)(xrow + j * 4);
    wh2[0] = *(const uint4*)(whp);     wh2[1] = *(const uint4*)(whp + 8);
    wl2[0] = *(const uint4*)(wlp);     wl2[1] = *(const uint4*)(wlp + 8);

    for (int c = 0; c < 8; c++) {
        // store staged regs to smem (convert x)
        #pragma unroll
        for (int j = 0; j < 4; j++) {
            float4 f = xr[j];
            __nv_bfloat16 h0 = __float2bfloat16(f.x), h1 = __float2bfloat16(f.y);
            __nv_bfloat16 h2 = __float2bfloat16(f.z), h3 = __float2bfloat16(f.w);
            __nv_bfloat16 l0 = __float2bfloat16(f.x - __bfloat162float(h0));
            __nv_bfloat16 l1 = __float2bfloat16(f.y - __bfloat162float(h1));
            __nv_bfloat16 l2 = __float2bfloat16(f.z - __bfloat162float(h2));
            __nv_bfloat16 l3 = __float2bfloat16(f.w - __bfloat162float(h3));
            *(uint2*)(arow_h + j * 8) = make_uint2(packbf(h0, h1), packbf(h2, h3));
            *(uint2*)(arow_l + j * 8) = make_uint2(packbf(l0, l1), packbf(l2, l3));
        }
        *(uint4*)(brow_h)      = wh2[0];
        *(uint4*)(brow_h + 16) = wh2[1];
        *(uint4*)(brow_l)      = wl2[0];
        *(uint4*)(brow_l + 16) = wl2[1];
        __syncthreads();

        // prefetch next chunk while MMAs run
        if (c < 7) {
            int k1 = (c + 1) * 64;
            #pragma unroll
            for (int j = 0; j < 4; j++) xr[j] = *(const float4*)(xrow + k1 + j * 4);
            wh2[0] = *(const uint4*)(whp + k1);  wh2[1] = *(const uint4*)(whp + k1 + 8);
            wl2[0] = *(const uint4*)(wlp + k1);  wl2[1] = *(const uint4*)(wlp + k1 + 8);
        }

        #pragma unroll
        for (int ks = 0; ks < 4; ks++) {
            int ko = ks * 16;
            uint32_t ah[2][4], al[2][4];
            #pragma unroll
            for (int mf = 0; mf < 2; mf++) {
                uint32_t aa = sb + (a_rb + mf * 16) * RSTR + (ko + a_c) * 2;
                LDSM4(ah[mf], aa + SA_H);
                LDSM4(al[mf], aa + SA_L);
            }
            #pragma unroll
            for (int nf2 = 0; nf2 < 2; nf2++) {
                uint32_t bh[4], bl[4];
                uint32_t ba = sb + (b_rb + nf2 * 16) * RSTR + (ko + b_c) * 2;
                LDSM4(bh, ba + SB_H);
                LDSM4(bl, ba + SB_L);
                #pragma unroll
                for (int mf = 0; mf < 2; mf++) {
                    MMA16816(acc[mf][2 * nf2],     ah[mf], bh[0], bh[1]);
                    MMA16816(acc[mf][2 * nf2],     ah[mf], bl[0], bl[1]);
                    MMA16816(acc[mf][2 * nf2],     al[mf], bh[0], bh[1]);
                    MMA16816(acc[mf][2 * nf2 + 1], ah[mf], bh[2], bh[3]);
                    MMA16816(acc[mf][2 * nf2 + 1], ah[mf], bl[2], bl[3]);
                    MMA16816(acc[mf][2 * nf2 + 1], al[mf], bh[2], bh[3]);
                }
            }
        }
        __syncthreads();
    }

    // epilogue: bias, z store, s/t partials
    #pragma unroll
    for (int r4 = 0; r4 < 4; r4++) {
        int mf = r4 >> 1, half = r4 & 1;
        int rloc = warp_m * 32 + mf * 16 + half * 8 + (lane >> 2);
        int row_g = m0 + rloc;
        float sp = 0.f, tp = 0.f;
        #pragma unroll
        for (int nf = 0; nf < 4; nf++) {
            int col = warp_n * 32 + nf * 8 + (lane & 3) * 2;
            float z0 = acc[mf][nf][half * 2]     + bias[col];
            float z1 = acc[mf][nf][half * 2 + 1] + bias[col + 1];
            *(float2*)(g_z + (size_t)row_g * FD + col) = make_float2(z0, z1);
            sp = fmaf(z0, att[col], fmaf(z1, att[col + 1], sp));
            tp = fmaf(z0, att[FD + col], fmaf(z1, att[FD + col + 1], tp));
        }
        sp += __shfl_xor_sync(0xffffffffu, sp, 1);
        sp += __shfl_xor_sync(0xffffffffu, sp, 2);
        tp += __shfl_xor_sync(0xffffffffu, tp, 1);
        tp += __shfl_xor_sync(0xffffffffu, tp, 2);
        if ((lane & 3) == 0) {
            *(float*)(smem + SP_S + (warp_n * 128 + rloc) * 4) = sp;
            *(float*)(smem + SP_T + (warp_n * 128 + rloc) * 4) = tp;
        }
    }
    __syncthreads();
    if (tid < 128) {
        float s = 0.f, t = 0.f;
        #pragma unroll
        for (int q = 0; q < 4; q++) {
            s += *(float*)(smem + SP_S + (q * 128 + tid) * 4);
            t += *(float*)(smem + SP_T + (q * 128 + tid) * 4);
        }
        g_s[m0 + tid] = s;
        g_t[m0 + tid] = t;
        atomicAdd(&g_cnt[bucket_of(t)], 1);
    }
}

// ---------------- 3. parallel bucket prefix ----------------
__global__ void k_prefix() {
    __shared__ int wsum[8];
    int t = threadIdx.x, lane = t & 31, wid = t >> 5;
    int c[32];
    const int4* c4 = (const int4*)g_cnt;
    int s = 0;
    #pragma unroll
    for (int i = 0; i < 8; i++) {
        int4 v = c4[t * 8 + i];
        c[4 * i] = v.x; c[4 * i + 1] = v.y; c[4 * i + 2] = v.z; c[4 * i + 3] = v.w;
        s += v.x + v.y + v.z + v.w;
    }
    int sc = s;
    #pragma unroll
    for (int o = 1; o < 32; o <<= 1) {
        int n = __shfl_up_sync(0xffffffffu, sc, o);
        if (lane >= o) sc += n;
    }
    if (lane == 31) wsum[wid] = sc;
    __syncthreads();
    int woff = 0;
    #pragma unroll
    for (int i = 0; i < 8; i++) if (i < wid) woff += wsum[i];
    int run = woff + sc - s;
    #pragma unroll
    for (int i = 0; i < 32; i++) {
        g_bstart[t * 32 + i] = run;
        g_cursor[t * 32 + i] = run;
        run += c[i];
    }
    if (t == 255) g_bstart[NB] = NR;
}

// ---------------- 4. fused scatter + permuted-z materialize ----------------
__global__ void k_scatter() {
    int gw = (blockIdx.x * blockDim.x + threadIdx.x) >> 5;
    int lane = threadIdx.x & 31;
    if (gw >= NR) return;
    int slot = 0;
    float tv = 0.f;
    if (lane == 0) {
        tv = g_t[gw];
        slot = atomicAdd(&g_cursor[bucket_of(tv)], 1);
    }
    slot = __shfl_sync(0xffffffffu, slot, 0);
    float4 zv = *(const float4*)(g_z + (size_t)gw * FD + lane * 4);
    *(float4*)(g_zp + (size_t)slot * FD + lane * 4) = zv;
    if (lane == 0) {
        g_tp[slot] = tv;
        g_etp[slot] = expf(tv);
    }
}

// ---------------- 5. chunked scans ----------------
__global__ void k_s1() {
    int c = blockIdx.x, f = threadIdx.x;
    int base = c * CH;
    float aZ = 0.f, aEZ = 0.f, aE = 0.f;
    #pragma unroll 8
    for (int r = 0; r < CH; r++) {
        int m = base + r;
        float et = g_etp[m];
        float zv = g_zp[(size_t)m * FD + f];
        aZ += zv;
        aEZ = fmaf(et, zv, aEZ);
        aE += et;
    }
    g_chZ[c * FD + f] = aZ;
    g_chEZ[c * FD + f] = aEZ;
    if (f == 0) g_chE[c] = aE;
}

__global__ void k_s2() {
    int f = threadIdx.x;
    float run = 0.f;
    #pragma unroll 8
    for (int c = 0; c < NCH; c++) { g_ofZ[c * FD + f] = run; run += g_chZ[c * FD + f]; }
    g_PZ[(size_t)NR * FD + f] = run;
    float re = 0.f;
    #pragma unroll 8
    for (int c = NCH - 1; c >= 0; c--) { g_ofEZ[c * FD + f] = re; re += g_chEZ[c * FD + f]; }
    g_SEZ[(size_t)NR * FD + f] = 0.f;
    if (f == 0) {
        float rE = 0.f;
        for (int c = NCH - 1; c >= 0; c--) { g_ofE[c] = rE; rE += g_chE[c]; }
        g_SE[NR] = 0.f;
    }
}

__global__ void k_s3() {
    int c = blockIdx.x, f = threadIdx.x, base = c * CH;
    float aZ = g_ofZ[c * FD + f];
    #pragma unroll 8
    for (int r = 0; r < CH; r++) {
        int m = base + r;
        g_PZ[(size_t)m * FD + f] = aZ;
        aZ += g_zp[(size_t)m * FD + f];
    }
    float aEZ = g_ofEZ[c * FD + f];
    float aE = g_ofE[c];
    #pragma unroll 8
    for (int r = CH - 1; r >= 0; r--) {
        int m = base + r;
        float et = g_etp[m];
        aEZ = fmaf(et, g_zp[(size_t)m * FD + f], aEZ);
        g_SEZ[(size_t)m * FD + f] = aEZ;
        if (f == 0) { aE += et; g_SE[m] = aE; }
    }
}

// ---------------- 6. per-row combine + row softmax (1 row / block) ---------
__global__ void k_final(float* __restrict__ out) {
    __shared__ float rmax[4], rsum[4];
    int f = threadIdx.x, lane = f & 31, wid = f >> 5;
    int i = blockIdx.x;
    float si = g_s[i];
    float th = -si;
    float es = expf(si);
    int b = bucket_of(th);
    int klo = g_bstart[b], khi = g_bstart[b + 1];
    float D = (float)klo + es * g_SE[khi];
    float num = g_PZ[(size_t)klo * FD + f] + es * g_SEZ[(size_t)khi * FD + f];
    for (int m = klo; m < khi; m++) {
        float tj = g_tp[m];
        float zv = g_zp[(size_t)m * FD + f];
        if (tj <= th) { num += zv; D += 1.f; }
        else { float w = es * g_etp[m]; num = fmaf(w, zv, num); D += w; }
    }
    float z2 = num / D + g_z[(size_t)i * FD + f];
    float mx = z2;
    #pragma unroll
    for (int o = 16; o; o >>= 1) mx = fmaxf(mx, __shfl_xor_sync(0xffffffffu, mx, o));
    if (lane == 0) rmax[wid] = mx;
    __syncthreads();
    mx = fmaxf(fmaxf(rmax[0], rmax[1]), fmaxf(rmax[2], rmax[3]));
    float ex = expf(z2 - mx);
    float sm = ex;
    #pragma unroll
    for (int o = 16; o; o >>= 1) sm += __shfl_xor_sync(0xffffffffu, sm, o);
    if (lane == 0) rsum[wid] = sm;
    __syncthreads();
    sm = rsum[0] + rsum[1] + rsum[2] + rsum[3];
    out[(size_t)i * FD + f] = ex / sm;
}

// ---------------- launch ----------------
extern "C" void kernel_launch(void* const* d_in, const int* in_sizes, int n_in,
                              void* d_out, int out_size) {
    const float* x   = (const float*)d_in[0];
    const float* v   = (const float*)d_in[1];
    const float* g   = (const float*)d_in[2];
    const float* b   = (const float*)d_in[3];
    const float* att = (const float*)d_in[4];
    float* out = (float*)d_out;

    static int smem_set = 0;
    if (!smem_set) {
        cudaFuncSetAttribute(k_gemm, cudaFuncAttributeMaxDynamicSharedMemorySize, SM_TOT);
        smem_set = 1;
    }

    k_w<<<FD, 128>>>(v, g);
    k_gemm<<<NR / 128, 512, SM_TOT>>>(x, b, att);
    k_prefix<<<1, 256>>>();
    k_scatter<<<NR / 8, 256>>>();
    k_s1<<<NCH, FD>>>();
    k_s2<<<1, FD>>>();
    k_s3<<<NCH, FD>>>();
    k_final<<<NR, FD>>>(out);
}